// round 10
// baseline (speedup 1.0000x reference)
#include <cuda_runtime.h>
#include <cuda_bf16.h>
#include <math.h>

// Problem constants
#define BB 32
#define CC 16
#define LL 4096
#define SS 64
#define KK 64
#define WW 4033            // LL - SS + 1

#define W_TILE 256
#define NT 512             // 16 warps: wid&7 -> m-rows (wid&7)*32, wid>>3 -> k-half
#define CLEN 4352          // padded per-copy length (elements) in g_x8
#define CPYSTR 656         // bytes per shifted copy in smem (>=328 elems, ==16 mod 128)
#define X8_HI (8 * CPYSTR)          // 5248: hi block (8 copies)
#define X8_BUF (2 * X8_HI)          // 10496: hi + lo
#define X8_CSTEP (8 * CLEN * 2)     // 69632 bytes per c in g_x8

// ---------------- dynamic smem layout (bytes) ----------------
#define OFF_X8  0                         // 2 x 10496 = 20992 (double-buffered)
#define OFF_B   20992                     // 2 x 16384 = 32768
#define OFF_INV 53760                     // CC*W_TILE floats = 16384
#define SMEM_BYTES 70144

typedef unsigned int u32;

// Global scratch
__device__ float g_invn[(size_t)BB * CC * WW];            // 1/max(||win||,eps), 0 for w>=WW handled at stage
__device__ __align__(16) unsigned char g_shb[CC * 16384]; // per-c swizzled B image: hi @0, lo @8192
// 8 shifted bf16 copies of x: [h(hi/lo)][b*CC+c][p(0..7)][l(0..CLEN)]
__device__ __align__(16) __nv_bfloat16 g_x8[(size_t)2 * BB * CC * 8 * CLEN];  // 71 MB

// ---------------- helpers ----------------
__device__ __forceinline__ u32 smem_u32(const void* p) {
    u32 a;
    asm("{ .reg .u64 t; cvta.to.shared.u64 t, %1; cvt.u32.u64 %0, t; }" : "=r"(a) : "l"(p));
    return a;
}
__device__ __forceinline__ u32 swz128(u32 off) { return off ^ ((off >> 3) & 0x70); }

__device__ __forceinline__ void ldsm4(u32& r0, u32& r1, u32& r2, u32& r3, u32 addr) {
    asm volatile("ldmatrix.sync.aligned.m8n8.x4.shared.b16 {%0,%1,%2,%3}, [%4];"
                 : "=r"(r0), "=r"(r1), "=r"(r2), "=r"(r3) : "r"(addr));
}
__device__ __forceinline__ void mma_bf16(float* d, u32 a0, u32 a1, u32 a2, u32 a3,
                                         u32 b0, u32 b1) {
    asm volatile(
        "mma.sync.aligned.m16n8k16.row.col.f32.bf16.bf16.f32 "
        "{%0,%1,%2,%3}, {%4,%5,%6,%7}, {%8,%9}, {%0,%1,%2,%3};"
        : "+f"(d[0]), "+f"(d[1]), "+f"(d[2]), "+f"(d[3])
        : "r"(a0), "r"(a1), "r"(a2), "r"(a3), "r"(b0), "r"(b1));
}

// ---------------------------------------------------------------------------
// Prep 1: normalize shapelets, bf16 split, write swizzled B image per c.
// ---------------------------------------------------------------------------
__global__ void norm_shapelets_kernel(const float* __restrict__ sh) {
    int row  = blockIdx.x;          // c*KK + k
    int c    = row / KK;
    int k    = row - c * KK;
    int lane = threadIdx.x;
    const float* p = sh + (size_t)row * SS;
    float v0 = p[lane];
    float v1 = p[lane + 32];
    float ss = v0 * v0 + v1 * v1;
    #pragma unroll
    for (int o = 16; o > 0; o >>= 1) ss += __shfl_xor_sync(0xffffffffu, ss, o);
    float inv = 1.0f / fmaxf(sqrtf(ss), 1e-8f);

    unsigned char* img = g_shb + c * 16384;
    #pragma unroll
    for (int h = 0; h < 2; ++h) {
        int s = lane + 32 * h;
        float vn = (h ? v1 : v0) * inv;
        __nv_bfloat16 hb = __float2bfloat16(vn);
        float hf = __bfloat162float(hb);
        __nv_bfloat16 lb = __float2bfloat16(vn - hf);
        u32 sw = swz128((u32)(k * 128 + s * 2));
        *(unsigned short*)(img + sw)        = __bfloat16_as_ushort(hb);
        *(unsigned short*)(img + 8192 + sw) = __bfloat16_as_ushort(lb);
    }
}

// ---------------------------------------------------------------------------
// Prep 2: inverse window norms, chunked sliding sum-of-squares.
// ---------------------------------------------------------------------------
__device__ __forceinline__ float inv_norm(float ss) {
    return (ss > 1e-16f) ? rsqrtf(ss) : 1e8f;
}
__global__ void win_invnorm_kernel(const float* __restrict__ x) {
    __shared__ float xs[LL];
    int row = blockIdx.x;           // b*CC + c
    const float* xr = x + (size_t)row * LL;
    for (int i = threadIdx.x; i < LL; i += blockDim.x) xs[i] = xr[i];
    __syncthreads();
    int wbase = threadIdx.x * 16;
    if (wbase < WW) {
        float* dst = g_invn + (size_t)row * WW;
        float ss = 0.0f;
        #pragma unroll
        for (int s = 0; s < SS; ++s) { float v = xs[wbase + s]; ss = fmaf(v, v, ss); }
        dst[wbase] = inv_norm(ss);
        #pragma unroll
        for (int j = 1; j < 16; ++j) {
            int w = wbase + j;
            if (w < WW) {
                float a = xs[w + SS - 1], s0 = xs[w - 1];
                ss = fmaf(a, a, ss);
                ss = fmaf(-s0, s0, ss);
                dst[w] = inv_norm(ss);
            }
        }
    }
}

// ---------------------------------------------------------------------------
// Prep 3: bf16 hi/lo split of x into 8 element-shifted copies (zero-padded).
// grid = BB*CC, 256 threads.
// ---------------------------------------------------------------------------
__global__ void xsplit8_kernel(const float* __restrict__ x) {
    __shared__ float xs[LL];
    int bc = blockIdx.x;
    const float* xr = x + (size_t)bc * LL;
    for (int i = threadIdx.x; i < LL; i += blockDim.x) xs[i] = xr[i];
    __syncthreads();
    __nv_bfloat16* gx = g_x8;
    #pragma unroll 1
    for (int p = 0; p < 8; ++p) {
        size_t hb = ((size_t)(0 * BB * CC + bc) * 8 + p) * CLEN;
        size_t lb = ((size_t)(1 * BB * CC + bc) * 8 + p) * CLEN;
        for (int base = threadIdx.x * 8; base < CLEN; base += blockDim.x * 8) {
            __nv_bfloat16 hv[8], lv[8];
            #pragma unroll
            for (int e = 0; e < 8; ++e) {
                int idx = base + e + p;
                float v = (idx < LL) ? xs[idx] : 0.0f;
                hv[e] = __float2bfloat16(v);
                lv[e] = __float2bfloat16(v - __bfloat162float(hv[e]));
            }
            *(uint4*)(gx + hb + base) = *(uint4*)hv;
            *(uint4*)(gx + lb + base) = *(uint4*)lv;
        }
    }
}

__global__ void zero_out_kernel(float* __restrict__ out) {
    out[blockIdx.x * 256 + threadIdx.x] = 0.0f;
}

// ---------------------------------------------------------------------------
// Main: per (b, 256-w tile). 16 warps; warp = m32 (rows (wid&7)*32..+32) x n32
// (cols (wid>>3)*32..+32). A fragments ldmatrix'd directly from linear shifted
// x copies (Hankel — no im2col build); inv folded per-c in fp32 epilogue.
// ---------------------------------------------------------------------------
__global__ void __launch_bounds__(NT, 1)
max_cossim_kernel(float* __restrict__ out) {
    extern __shared__ unsigned char smem[];
    const u32 sbase = smem_u32(smem);
    const int b  = blockIdx.y;
    const int w0 = blockIdx.x * W_TILE;
    const int t  = threadIdx.x;
    const int wid = t >> 5, lane = t & 31;

    float* invs = (float*)(smem + OFF_INV);

    // Stage inv-norm tile (0 for OOB windows -> dead rows).
    for (int idx = t; idx < CC * W_TILE; idx += NT) {
        int c = idx >> 8, j = idx & (W_TILE - 1);
        int gw = w0 + j;
        invs[idx] = (gw < WW) ? g_invn[((size_t)b * CC + c) * WW + gw] : 0.0f;
    }

    // ---- X8 staging units (656 x 16B per buffer fill): precompute (h,p,q) ----
    // unit u: h = u>=328, r = u - 328h, p = r/41, q = r%41
    int hA = (t >= 328) ? 1 : 0;
    int rA = t - 328 * hA;
    int pA = rA / 41, qA = rA - 41 * pA;
    const unsigned char* srcA = (const unsigned char*)g_x8 +
        2 * (((size_t)(hA * BB * CC + b * CC) * 8 + pA) * CLEN + w0 + qA * 8);
    const u32 dstA = (u32)(hA * X8_HI + pA * CPYSTR + qA * 16);
    int rB = t + 512 - 328;                 // second unit (h=1 always); valid if t<144
    int pB = rB / 41, qB = rB - 41 * pB;
    const unsigned char* srcB = (const unsigned char*)g_x8 +
        2 * (((size_t)(BB * CC + b * CC) * 8 + pB) * CLEN + w0 + qB * 8);
    const u32 dstB = (u32)(X8_HI + pB * CPYSTR + qB * 16);

    auto stage = [&](int cc, int bf) {
        unsigned char* xdst = smem + OFF_X8 + bf * X8_BUF;
        *(uint4*)(xdst + dstA) = *(const uint4*)(srcA + (size_t)cc * X8_CSTEP);
        if (t < 144)
            *(uint4*)(xdst + dstB) = *(const uint4*)(srcB + (size_t)cc * X8_CSTEP);
        const unsigned char* bsrc = g_shb + (size_t)cc * 16384;
        unsigned char* bdst = smem + OFF_B + bf * 16384;
        *(uint4*)(bdst + t * 16)         = *(const uint4*)(bsrc + t * 16);
        *(uint4*)(bdst + (t + 512) * 16) = *(const uint4*)(bsrc + (t + 512) * 16);
    };

    stage(0, 0);
    __syncthreads();

    // A fragment address: copy index = lane&7 (shift makes rows 16B-aligned).
    const u32 a_base = (u32)((lane & 7) * CPYSTR +
        2 * ((wid & 7) * 32 + 8 * ((lane >> 3) & 1) + 8 * ((lane >> 4) & 1)));
    const int rx    = lane & 7;
    const int bn8   = (lane >> 4) & 1;
    const int bhalf = (lane >> 3) & 1;
    const int pbase = (wid >> 3) * 2;       // k-half ntile-pair base

    float acc[32];                          // [m(2)][nt(4)][4]
    #pragma unroll
    for (int i = 0; i < 32; ++i) acc[i] = 0.0f;

    for (int c = 0; c < CC; ++c) {
        const int buf = c & 1;
        if (c + 1 < CC) stage(c + 1, buf ^ 1);

        float dot[32];
        #pragma unroll
        for (int i = 0; i < 32; ++i) dot[i] = 0.0f;

        const u32 Xb = sbase + OFF_X8 + buf * X8_BUF;
        const u32 Bb = sbase + OFF_B + buf * 16384;

        // Hankel roll: frag(jj) for m0 at k-step jj == frag for m1 at jj-1.
        u32 ch0, ch1, ch2, ch3, cl0, cl1, cl2, cl3;   // current (m0) hi/lo
        ldsm4(ch0, ch1, ch2, ch3, Xb + a_base);
        ldsm4(cl0, cl1, cl2, cl3, Xb + a_base + X8_HI);
        #pragma unroll
        for (int j = 0; j < 4; ++j) {
            u32 nh0, nh1, nh2, nh3, nl0, nl1, nl2, nl3;  // next (= m1 at this j)
            ldsm4(nh0, nh1, nh2, nh3, Xb + a_base + 32 * (j + 1));
            ldsm4(nl0, nl1, nl2, nl3, Xb + a_base + 32 * (j + 1) + X8_HI);
            u32 bch = (u32)(((2 * j + bhalf) ^ rx) * 16);
            #pragma unroll
            for (int p = 0; p < 2; ++p) {
                u32 boff = (u32)(((pbase + p) * 16 + bn8 * 8 + rx) * 128) + bch;
                u32 bh0, bh1, bh2, bh3, bl0, bl1, bl2, bl3;
                ldsm4(bh0, bh1, bh2, bh3, Bb + boff);
                ldsm4(bl0, bl1, bl2, bl3, Bb + 8192 + boff);
                float* d00 = dot + (0 * 4 + 2 * p) * 4;
                float* d01 = dot + (0 * 4 + 2 * p + 1) * 4;
                float* d10 = dot + (1 * 4 + 2 * p) * 4;
                float* d11 = dot + (1 * 4 + 2 * p + 1) * 4;
                mma_bf16(d00, ch0, ch1, ch2, ch3, bh0, bh1);   // hi*hi
                mma_bf16(d01, ch0, ch1, ch2, ch3, bh2, bh3);
                mma_bf16(d10, nh0, nh1, nh2, nh3, bh0, bh1);
                mma_bf16(d11, nh0, nh1, nh2, nh3, bh2, bh3);
                mma_bf16(d00, ch0, ch1, ch2, ch3, bl0, bl1);   // hi*lo
                mma_bf16(d01, ch0, ch1, ch2, ch3, bl2, bl3);
                mma_bf16(d10, nh0, nh1, nh2, nh3, bl0, bl1);
                mma_bf16(d11, nh0, nh1, nh2, nh3, bl2, bl3);
                mma_bf16(d00, cl0, cl1, cl2, cl3, bh0, bh1);   // lo*hi
                mma_bf16(d01, cl0, cl1, cl2, cl3, bh2, bh3);
                mma_bf16(d10, nl0, nl1, nl2, nl3, bh0, bh1);
                mma_bf16(d11, nl0, nl1, nl2, nl3, bh2, bh3);
            }
            ch0 = nh0; ch1 = nh1; ch2 = nh2; ch3 = nh3;  // renamed away by unroll
            cl0 = nl0; cl1 = nl1; cl2 = nl2; cl3 = nl3;
        }

        // Fold: acc += inv[c, row] * dot (rows: m0 -> g,g+8; m1 -> g+16,g+24)
        {
            const int g = lane >> 2;
            const float* ivp = invs + c * W_TILE + (wid & 7) * 32;
            float iv0 = ivp[g], iv1 = ivp[g + 8], iv2 = ivp[g + 16], iv3 = ivp[g + 24];
            #pragma unroll
            for (int nt = 0; nt < 4; ++nt) {
                acc[nt * 4 + 0]      = fmaf(iv0, dot[nt * 4 + 0],      acc[nt * 4 + 0]);
                acc[nt * 4 + 1]      = fmaf(iv0, dot[nt * 4 + 1],      acc[nt * 4 + 1]);
                acc[nt * 4 + 2]      = fmaf(iv1, dot[nt * 4 + 2],      acc[nt * 4 + 2]);
                acc[nt * 4 + 3]      = fmaf(iv1, dot[nt * 4 + 3],      acc[nt * 4 + 3]);
                acc[16 + nt * 4 + 0] = fmaf(iv2, dot[16 + nt * 4 + 0], acc[16 + nt * 4 + 0]);
                acc[16 + nt * 4 + 1] = fmaf(iv2, dot[16 + nt * 4 + 1], acc[16 + nt * 4 + 1]);
                acc[16 + nt * 4 + 2] = fmaf(iv3, dot[16 + nt * 4 + 2], acc[16 + nt * 4 + 2]);
                acc[16 + nt * 4 + 3] = fmaf(iv3, dot[16 + nt * 4 + 3], acc[16 + nt * 4 + 3]);
            }
        }
        __syncthreads();
    }

    // ---- epilogue: max over w per k ----
    float cm[8];
    #pragma unroll
    for (int nt = 0; nt < 4; ++nt) {
        cm[2 * nt] = fmaxf(fmaxf(acc[nt * 4 + 0], acc[nt * 4 + 2]),
                           fmaxf(acc[16 + nt * 4 + 0], acc[16 + nt * 4 + 2]));
        cm[2 * nt + 1] = fmaxf(fmaxf(acc[nt * 4 + 1], acc[nt * 4 + 3]),
                               fmaxf(acc[16 + nt * 4 + 1], acc[16 + nt * 4 + 3]));
    }
    #pragma unroll
    for (int m = 4; m < 32; m <<= 1) {
        #pragma unroll
        for (int i = 0; i < 8; ++i)
            cm[i] = fmaxf(cm[i], __shfl_xor_sync(0xffffffffu, cm[i], m));
    }
    float* red = (float*)(smem + OFF_X8);   // [16 warps][64 cols]
    if (lane < 4) {
        int kb = (wid >> 3) * 32;
        #pragma unroll
        for (int nt = 0; nt < 4; ++nt) {
            red[wid * 64 + kb + nt * 8 + lane * 2 + 0] = cm[2 * nt];
            red[wid * 64 + kb + nt * 8 + lane * 2 + 1] = cm[2 * nt + 1];
        }
    }
    __syncthreads();
    if (t < KK) {
        int g0 = (t >> 5) * 8;              // warps holding this k-half
        float m = 0.0f;                     // relu floor
        #pragma unroll
        for (int i = 0; i < 8; ++i) m = fmaxf(m, red[(g0 + i) * 64 + t]);
        m *= (1.0f / (float)CC);
        // m >= 0: float bits monotone, int atomicMax exact (out zero-initialized).
        atomicMax((int*)&out[b * KK + t], __float_as_int(m));
    }
}

// ---------------------------------------------------------------------------
// Launch
// ---------------------------------------------------------------------------
extern "C" void kernel_launch(void* const* d_in, const int* in_sizes, int n_in,
                              void* d_out, int out_size) {
    const float* x  = (const float*)d_in[0];   // (32,16,4096) f32
    const float* sh = (const float*)d_in[1];   // (16,64,64)  f32
    float* out = (float*)d_out;                // (32,1,64)   f32

    cudaFuncSetAttribute(max_cossim_kernel,
                         cudaFuncAttributeMaxDynamicSharedMemorySize, SMEM_BYTES);

    norm_shapelets_kernel<<<CC * KK, 32>>>(sh);
    win_invnorm_kernel<<<BB * CC, 256>>>(x);
    xsplit8_kernel<<<BB * CC, 256>>>(x);
    zero_out_kernel<<<(BB * KK) / 256, 256>>>(out);

    dim3 grid((WW + W_TILE - 1) / W_TILE, BB);   // (16, 32)
    max_cossim_kernel<<<grid, NT, SMEM_BYTES>>>(out);
}

// round 11
// speedup vs baseline: 1.2267x; 1.2267x over previous
#include <cuda_runtime.h>
#include <cuda_bf16.h>
#include <math.h>

// Problem constants
#define BB 32
#define CC 16
#define LL 4096
#define SS 64
#define KK 64
#define WW 4033            // LL - SS + 1

#define W_TILE 256
#define NT 512             // 16 warps: wid&7 -> m32 tile, wid>>3 -> k-half (n32)
#define XS_STRIDE 360      // f32 staging elems per c (need 354)
#define PLEN_B 704         // bytes per parity copy (352 elems; 176 words, ==16 mod 32 banks)

// ---------------- dynamic smem layout (bytes) ----------------
#define OFF_XHL 0                              // [c][h][p] parity copies: 16*2*2*704 = 45056
#define OFF_B   45056                          // 3 x 16384 = 49152 (triple-buffered B)
#define OFF_INV 94208                          // CC*W_TILE floats = 16384
#define OFF_XS  110592                         // CC*XS_STRIDE f32 = 23040
#define SMEM_BYTES 133632

typedef unsigned int u32;

// Global scratch
__device__ float g_invn[(size_t)BB * CC * WW];            // 1/max(||win||,eps)
__device__ __align__(16) unsigned char g_shb[CC * 16384]; // per-c swizzled B image: hi @0, lo @8192

// ---------------- helpers ----------------
__device__ __forceinline__ u32 smem_u32(const void* p) {
    u32 a;
    asm("{ .reg .u64 t; cvta.to.shared.u64 t, %1; cvt.u32.u64 %0, t; }" : "=r"(a) : "l"(p));
    return a;
}
__device__ __forceinline__ u32 swz128(u32 off) { return off ^ ((off >> 3) & 0x70); }

__device__ __forceinline__ void ldsm4(u32& r0, u32& r1, u32& r2, u32& r3, u32 addr) {
    asm volatile("ldmatrix.sync.aligned.m8n8.x4.shared.b16 {%0,%1,%2,%3}, [%4];"
                 : "=r"(r0), "=r"(r1), "=r"(r2), "=r"(r3) : "r"(addr));
}
__device__ __forceinline__ u32 lds32(u32 addr) {
    u32 v;
    asm volatile("ld.shared.b32 %0, [%1];" : "=r"(v) : "r"(addr));
    return v;
}
__device__ __forceinline__ void mma_bf16(float* d, u32 a0, u32 a1, u32 a2, u32 a3,
                                         u32 b0, u32 b1) {
    asm volatile(
        "mma.sync.aligned.m16n8k16.row.col.f32.bf16.bf16.f32 "
        "{%0,%1,%2,%3}, {%4,%5,%6,%7}, {%8,%9}, {%0,%1,%2,%3};"
        : "+f"(d[0]), "+f"(d[1]), "+f"(d[2]), "+f"(d[3])
        : "r"(a0), "r"(a1), "r"(a2), "r"(a3), "r"(b0), "r"(b1));
}

// ---------------------------------------------------------------------------
// Prep 1: normalize shapelets, bf16 split, write swizzled B image per c.
// Blocks 0..63 additionally zero the 2048-float output.
// ---------------------------------------------------------------------------
__global__ void norm_shapelets_kernel(const float* __restrict__ sh,
                                      float* __restrict__ out) {
    int row  = blockIdx.x;          // c*KK + k
    int c    = row / KK;
    int k    = row - c * KK;
    int lane = threadIdx.x;
    if (row < 64) out[row * 32 + lane] = 0.0f;   // zero out (64*32 = 2048)
    const float* p = sh + (size_t)row * SS;
    float v0 = p[lane];
    float v1 = p[lane + 32];
    float ss = v0 * v0 + v1 * v1;
    #pragma unroll
    for (int o = 16; o > 0; o >>= 1) ss += __shfl_xor_sync(0xffffffffu, ss, o);
    float inv = 1.0f / fmaxf(sqrtf(ss), 1e-8f);

    unsigned char* img = g_shb + c * 16384;
    #pragma unroll
    for (int h = 0; h < 2; ++h) {
        int s = lane + 32 * h;
        float vn = (h ? v1 : v0) * inv;
        __nv_bfloat16 hb = __float2bfloat16(vn);
        float hf = __bfloat162float(hb);
        __nv_bfloat16 lb = __float2bfloat16(vn - hf);
        u32 sw = swz128((u32)(k * 128 + s * 2));
        *(unsigned short*)(img + sw)        = __bfloat16_as_ushort(hb);
        *(unsigned short*)(img + 8192 + sw) = __bfloat16_as_ushort(lb);
    }
}

// ---------------------------------------------------------------------------
// Prep 2: inverse window norms, chunked sliding sum-of-squares.
// ---------------------------------------------------------------------------
__device__ __forceinline__ float inv_norm(float ss) {
    return (ss > 1e-16f) ? rsqrtf(ss) : 1e8f;
}
__global__ void win_invnorm_kernel(const float* __restrict__ x) {
    __shared__ float xs[LL];
    int row = blockIdx.x;           // b*CC + c
    const float* xr = x + (size_t)row * LL;
    for (int i = threadIdx.x; i < LL; i += blockDim.x) xs[i] = xr[i];
    __syncthreads();
    int wbase = threadIdx.x * 16;
    if (wbase < WW) {
        float* dst = g_invn + (size_t)row * WW;
        float ss = 0.0f;
        #pragma unroll
        for (int s = 0; s < SS; ++s) { float v = xs[wbase + s]; ss = fmaf(v, v, ss); }
        dst[wbase] = inv_norm(ss);
        #pragma unroll
        for (int j = 1; j < 16; ++j) {
            int w = wbase + j;
            if (w < WW) {
                float a = xs[w + SS - 1], s0 = xs[w - 1];
                ss = fmaf(a, a, ss);
                ss = fmaf(-s0, s0, ss);
                dst[w] = inv_norm(ss);
            }
        }
    }
}

// ---------------------------------------------------------------------------
// Main: per (b, 256-w tile). Hankel A collapses to 22 u32 pair-loads per
// warp per c (a1==a2; a3(j)==a0(j+1)): t_i = (x[e0+8i], x[e0+8i+1]) via
// plain LDS.32 from a 2-parity hi/lo x buffer built ONCE in the prologue.
// B ldsm from triple-buffered staged image. inv folded per-c in fp32.
// ---------------------------------------------------------------------------
__global__ void __launch_bounds__(NT, 1)
max_cossim_kernel(const float* __restrict__ x, float* __restrict__ out) {
    extern __shared__ unsigned char smem[];
    const u32 sbase = smem_u32(smem);
    const int b  = blockIdx.y;
    const int w0 = blockIdx.x * W_TILE;
    const int t  = threadIdx.x;
    const int wid = t >> 5, lane = t & 31;

    float* xs   = (float*)(smem + OFF_XS);
    float* invs = (float*)(smem + OFF_INV);

    // ---- Prologue: stage raw x tile (f32) + inv tile ----
    const float* xb = x + (size_t)b * CC * LL;
    for (int idx = t; idx < CC * XS_STRIDE; idx += NT) {
        int c = idx / XS_STRIDE, j = idx - c * XS_STRIDE;
        int gw = w0 + j;
        xs[idx] = (gw < LL) ? xb[(size_t)c * LL + gw] : 0.0f;
    }
    for (int idx = t; idx < CC * W_TILE; idx += NT) {
        int c = idx >> 8, j = idx & (W_TILE - 1);
        int gw = w0 + j;
        invs[idx] = (gw < WW) ? g_invn[((size_t)b * CC + c) * WW + gw] : 0.0f;
    }
    __syncthreads();

    // ---- Build hi/lo parity copies for ALL channels (once) ----
    // word layout: [(c*2+h)*2+p][w], copy bytes PLEN_B; copy_p word w = pair
    // (x[2w+p], x[2w+p+1]) of channel c, h selects hi/lo split part.
    for (int idx = t; idx < 16 * 2 * 2 * 176; idx += NT) {
        int w = idx % 176;
        int r = idx / 176;            // (c*2+h)*2+p
        int p = r & 1, h = (r >> 1) & 1, c = r >> 2;
        int e = 2 * w + p;
        float v0 = xs[c * XS_STRIDE + e];
        float v1 = xs[c * XS_STRIDE + e + 1];
        __nv_bfloat162 hi = __float22bfloat162_rn(make_float2(v0, v1));
        u32 word;
        if (h == 0) {
            word = *(u32*)&hi;
        } else {
            float2 hf = __bfloat1622float2(hi);
            __nv_bfloat162 lo = __float22bfloat162_rn(make_float2(v0 - hf.x, v1 - hf.y));
            word = *(u32*)&lo;
        }
        *(u32*)(smem + OFF_XHL + r * PLEN_B + w * 4) = word;
    }

    // ---- Stage B for c=0,1 ----
    {
        const uint4* s0 = (const uint4*)(g_shb);
        const uint4* s1 = (const uint4*)(g_shb + 16384);
        uint4* d0 = (uint4*)(smem + OFF_B);
        uint4* d1 = (uint4*)(smem + OFF_B + 16384);
        d0[t] = s0[t]; d0[t + 512] = s0[t + 512];
        d1[t] = s1[t]; d1[t + 512] = s1[t + 512];
    }
    __syncthreads();

    // ---- Fragment addressing ----
    const int g  = lane >> 2, q = lane & 3;
    const int e0 = (wid & 7) * 32 + g + 2 * q;
    const int pA = g & 1;
    const int rx    = lane & 7;
    const int bn8   = (lane >> 4) & 1;
    const int bhalf = (lane >> 3) & 1;
    const int pbase = (wid >> 3) * 2;       // k-half ntile-pair base

    float acc[32];                          // [m(2)][nt(4)][4]
    #pragma unroll
    for (int i = 0; i < 32; ++i) acc[i] = 0.0f;

    int bufc = 0;
    for (int c = 0; c < CC; ++c) {
        const u32 Bb = sbase + OFF_B + bufc * 16384;

        // A: 11 t-loads per h (covers both m-tiles x 4 k-steps via Hankel).
        u32 th[11], tl[11];
        {
            u32 aH = sbase + OFF_XHL + (u32)(c * 4 + pA) * PLEN_B + (u32)(e0 - pA) * 2;
            u32 aL = aH + 2 * PLEN_B;
            #pragma unroll
            for (int i = 0; i < 11; ++i) {
                th[i] = lds32(aH + 16 * i);
                tl[i] = lds32(aL + 16 * i);
            }
        }

        float dot[32];
        #pragma unroll
        for (int i = 0; i < 32; ++i) dot[i] = 0.0f;

        #pragma unroll
        for (int j = 0; j < 4; ++j) {
            u32 bch = (u32)(((2 * j + bhalf) ^ rx) * 16);
            #pragma unroll
            for (int p = 0; p < 2; ++p) {
                u32 boff = (u32)(((pbase + p) * 16 + bn8 * 8 + rx) * 128) + bch;
                u32 bh0, bh1, bh2, bh3, bl0, bl1, bl2, bl3;
                ldsm4(bh0, bh1, bh2, bh3, Bb + boff);
                ldsm4(bl0, bl1, bl2, bl3, Bb + 8192 + boff);
                float* d00 = dot + (0 * 4 + 2 * p) * 4;
                float* d01 = dot + (0 * 4 + 2 * p + 1) * 4;
                float* d10 = dot + (1 * 4 + 2 * p) * 4;
                float* d11 = dot + (1 * 4 + 2 * p + 1) * 4;
                // hi*hi
                mma_bf16(d00, th[2*j], th[2*j+1], th[2*j+1], th[2*j+2], bh0, bh1);
                mma_bf16(d01, th[2*j], th[2*j+1], th[2*j+1], th[2*j+2], bh2, bh3);
                mma_bf16(d10, th[2*j+2], th[2*j+3], th[2*j+3], th[2*j+4], bh0, bh1);
                mma_bf16(d11, th[2*j+2], th[2*j+3], th[2*j+3], th[2*j+4], bh2, bh3);
                // hi*lo
                mma_bf16(d00, th[2*j], th[2*j+1], th[2*j+1], th[2*j+2], bl0, bl1);
                mma_bf16(d01, th[2*j], th[2*j+1], th[2*j+1], th[2*j+2], bl2, bl3);
                mma_bf16(d10, th[2*j+2], th[2*j+3], th[2*j+3], th[2*j+4], bl0, bl1);
                mma_bf16(d11, th[2*j+2], th[2*j+3], th[2*j+3], th[2*j+4], bl2, bl3);
                // lo*hi
                mma_bf16(d00, tl[2*j], tl[2*j+1], tl[2*j+1], tl[2*j+2], bh0, bh1);
                mma_bf16(d01, tl[2*j], tl[2*j+1], tl[2*j+1], tl[2*j+2], bh2, bh3);
                mma_bf16(d10, tl[2*j+2], tl[2*j+3], tl[2*j+3], tl[2*j+4], bh0, bh1);
                mma_bf16(d11, tl[2*j+2], tl[2*j+3], tl[2*j+3], tl[2*j+4], bh2, bh3);
            }
        }

        // Fold: acc += inv[c, row] * dot (rows g, g+8, g+16, g+24 of tile)
        {
            const float* ivp = invs + c * W_TILE + (wid & 7) * 32;
            float iv0 = ivp[g], iv1 = ivp[g + 8], iv2 = ivp[g + 16], iv3 = ivp[g + 24];
            #pragma unroll
            for (int nt = 0; nt < 4; ++nt) {
                acc[nt * 4 + 0]      = fmaf(iv0, dot[nt * 4 + 0],      acc[nt * 4 + 0]);
                acc[nt * 4 + 1]      = fmaf(iv0, dot[nt * 4 + 1],      acc[nt * 4 + 1]);
                acc[nt * 4 + 2]      = fmaf(iv1, dot[nt * 4 + 2],      acc[nt * 4 + 2]);
                acc[nt * 4 + 3]      = fmaf(iv1, dot[nt * 4 + 3],      acc[nt * 4 + 3]);
                acc[16 + nt * 4 + 0] = fmaf(iv2, dot[16 + nt * 4 + 0], acc[16 + nt * 4 + 0]);
                acc[16 + nt * 4 + 1] = fmaf(iv2, dot[16 + nt * 4 + 1], acc[16 + nt * 4 + 1]);
                acc[16 + nt * 4 + 2] = fmaf(iv3, dot[16 + nt * 4 + 2], acc[16 + nt * 4 + 2]);
                acc[16 + nt * 4 + 3] = fmaf(iv3, dot[16 + nt * 4 + 3], acc[16 + nt * 4 + 3]);
            }
        }

        // Stage B for c+2 into buffer (bufc+2)%3 (2-deep prefetch).
        if (c + 2 < CC) {
            int sb = bufc + 2; if (sb >= 3) sb -= 3;
            const uint4* src = (const uint4*)(g_shb + (size_t)(c + 2) * 16384);
            uint4* dst = (uint4*)(smem + OFF_B + sb * 16384);
            dst[t] = src[t]; dst[t + 512] = src[t + 512];
        }
        __syncthreads();
        bufc = (bufc == 2) ? 0 : bufc + 1;
    }

    // ---- epilogue: max over w per k ----
    float cm[8];
    #pragma unroll
    for (int nt = 0; nt < 4; ++nt) {
        cm[2 * nt] = fmaxf(fmaxf(acc[nt * 4 + 0], acc[nt * 4 + 2]),
                           fmaxf(acc[16 + nt * 4 + 0], acc[16 + nt * 4 + 2]));
        cm[2 * nt + 1] = fmaxf(fmaxf(acc[nt * 4 + 1], acc[nt * 4 + 3]),
                               fmaxf(acc[16 + nt * 4 + 1], acc[16 + nt * 4 + 3]));
    }
    #pragma unroll
    for (int m = 4; m < 32; m <<= 1) {
        #pragma unroll
        for (int i = 0; i < 8; ++i)
            cm[i] = fmaxf(cm[i], __shfl_xor_sync(0xffffffffu, cm[i], m));
    }
    float* red = (float*)(smem + OFF_XHL);  // [16 warps][64 cols]
    if (lane < 4) {
        int kb = (wid >> 3) * 32;
        #pragma unroll
        for (int nt = 0; nt < 4; ++nt) {
            red[wid * 64 + kb + nt * 8 + lane * 2 + 0] = cm[2 * nt];
            red[wid * 64 + kb + nt * 8 + lane * 2 + 1] = cm[2 * nt + 1];
        }
    }
    __syncthreads();
    if (t < KK) {
        int g0 = (t >> 5) * 8;              // warps holding this k-half
        float m = 0.0f;                     // relu floor
        #pragma unroll
        for (int i = 0; i < 8; ++i) m = fmaxf(m, red[(g0 + i) * 64 + t]);
        m *= (1.0f / (float)CC);
        // m >= 0: float bits monotone, int atomicMax exact (out zero-initialized).
        atomicMax((int*)&out[b * KK + t], __float_as_int(m));
    }
}

// ---------------------------------------------------------------------------
// Launch
// ---------------------------------------------------------------------------
extern "C" void kernel_launch(void* const* d_in, const int* in_sizes, int n_in,
                              void* d_out, int out_size) {
    const float* x  = (const float*)d_in[0];   // (32,16,4096) f32
    const float* sh = (const float*)d_in[1];   // (16,64,64)  f32
    float* out = (float*)d_out;                // (32,1,64)   f32

    cudaFuncSetAttribute(max_cossim_kernel,
                         cudaFuncAttributeMaxDynamicSharedMemorySize, SMEM_BYTES);

    norm_shapelets_kernel<<<CC * KK, 32>>>(sh, out);
    win_invnorm_kernel<<<BB * CC, 256>>>(x);

    dim3 grid((WW + W_TILE - 1) / W_TILE, BB);   // (16, 32)
    max_cossim_kernel<<<grid, NT, SMEM_BYTES>>>(x, out);
}

// round 12
// speedup vs baseline: 2.2701x; 1.8506x over previous
#include <cuda_runtime.h>
#include <cuda_fp16.h>
#include <math.h>

// Problem constants
#define BB 32
#define CC 16
#define LL 4096
#define SS 64
#define KK 64
#define WW 4033            // LL - SS + 1

#define W_TILE 256
#define NT 512             // 16 warps: wid&7 -> m32 tile, wid>>3 -> k-half (n32)
#define XS_STRIDE 360      // f32 staging elems per c (need 354)
#define PLEN_B 704         // bytes per parity copy (176 words)

// ---------------- dynamic smem layout (bytes) ----------------
#define OFF_XHL 0                              // [c][p] fp16 parity copies: 16*2*704 = 22528
#define OFF_B   22528                          // all-c B image: 16*8192 = 131072
#define OFF_INV 153600                         // CC*W_TILE floats = 16384
#define OFF_XS  169984                         // CC*XS_STRIDE f32 = 23040
#define SMEM_BYTES 193024

typedef unsigned int u32;

// Global scratch
__device__ float g_invn[(size_t)BB * CC * WW];            // 1/max(||win||,eps)
__device__ __align__(16) unsigned char g_shb[CC * 8192];  // per-c swizzled fp16 B image

// ---------------- helpers ----------------
__device__ __forceinline__ u32 smem_u32(const void* p) {
    u32 a;
    asm("{ .reg .u64 t; cvta.to.shared.u64 t, %1; cvt.u32.u64 %0, t; }" : "=r"(a) : "l"(p));
    return a;
}
__device__ __forceinline__ u32 swz128(u32 off) { return off ^ ((off >> 3) & 0x70); }

__device__ __forceinline__ void ldsm4(u32& r0, u32& r1, u32& r2, u32& r3, u32 addr) {
    asm volatile("ldmatrix.sync.aligned.m8n8.x4.shared.b16 {%0,%1,%2,%3}, [%4];"
                 : "=r"(r0), "=r"(r1), "=r"(r2), "=r"(r3) : "r"(addr));
}
__device__ __forceinline__ u32 lds32(u32 addr) {
    u32 v;
    asm volatile("ld.shared.b32 %0, [%1];" : "=r"(v) : "r"(addr));
    return v;
}
__device__ __forceinline__ void mma_f16(float* d, u32 a0, u32 a1, u32 a2, u32 a3,
                                        u32 b0, u32 b1) {
    asm volatile(
        "mma.sync.aligned.m16n8k16.row.col.f32.f16.f16.f32 "
        "{%0,%1,%2,%3}, {%4,%5,%6,%7}, {%8,%9}, {%0,%1,%2,%3};"
        : "+f"(d[0]), "+f"(d[1]), "+f"(d[2]), "+f"(d[3])
        : "r"(a0), "r"(a1), "r"(a2), "r"(a3), "r"(b0), "r"(b1));
}

// ---------------------------------------------------------------------------
// Prep 1: normalize shapelets, fp16, write swizzled B image per c.
// Blocks 0..63 additionally zero the 2048-float output.
// ---------------------------------------------------------------------------
__global__ void norm_shapelets_kernel(const float* __restrict__ sh,
                                      float* __restrict__ out) {
    int row  = blockIdx.x;          // c*KK + k
    int c    = row / KK;
    int k    = row - c * KK;
    int lane = threadIdx.x;
    if (row < 64) out[row * 32 + lane] = 0.0f;   // zero out (64*32 = 2048)
    const float* p = sh + (size_t)row * SS;
    float v0 = p[lane];
    float v1 = p[lane + 32];
    float ss = v0 * v0 + v1 * v1;
    #pragma unroll
    for (int o = 16; o > 0; o >>= 1) ss += __shfl_xor_sync(0xffffffffu, ss, o);
    float inv = 1.0f / fmaxf(sqrtf(ss), 1e-8f);

    unsigned char* img = g_shb + c * 8192;
    #pragma unroll
    for (int h = 0; h < 2; ++h) {
        int s = lane + 32 * h;
        float vn = (h ? v1 : v0) * inv;
        __half hv = __float2half_rn(vn);
        u32 sw = swz128((u32)(k * 128 + s * 2));
        *(unsigned short*)(img + sw) = *(unsigned short*)&hv;
    }
}

// ---------------------------------------------------------------------------
// Prep 2: inverse window norms, chunked sliding sum-of-squares.
// ---------------------------------------------------------------------------
__device__ __forceinline__ float inv_norm(float ss) {
    return (ss > 1e-16f) ? rsqrtf(ss) : 1e8f;
}
__global__ void win_invnorm_kernel(const float* __restrict__ x) {
    __shared__ float xs[LL];
    int row = blockIdx.x;           // b*CC + c
    const float* xr = x + (size_t)row * LL;
    for (int i = threadIdx.x; i < LL; i += blockDim.x) xs[i] = xr[i];
    __syncthreads();
    int wbase = threadIdx.x * 16;
    if (wbase < WW) {
        float* dst = g_invn + (size_t)row * WW;
        float ss = 0.0f;
        #pragma unroll
        for (int s = 0; s < SS; ++s) { float v = xs[wbase + s]; ss = fmaf(v, v, ss); }
        dst[wbase] = inv_norm(ss);
        #pragma unroll
        for (int j = 1; j < 16; ++j) {
            int w = wbase + j;
            if (w < WW) {
                float a = xs[w + SS - 1], s0 = xs[w - 1];
                ss = fmaf(a, a, ss);
                ss = fmaf(-s0, s0, ss);
                dst[w] = inv_norm(ss);
            }
        }
    }
}

// ---------------------------------------------------------------------------
// Main: per (b, 256-w tile). Single-term fp16 MMA (x raw in A; inv folded
// per-c in fp32). Hankel A = 11 broadcast LDS.32 per warp per c from fp16
// parity copies built once in the prologue. ALL of B (16 channels) resident
// in smem -> the 16-channel mainloop has NO stores and NO barriers.
// ---------------------------------------------------------------------------
__global__ void __launch_bounds__(NT, 1)
max_cossim_kernel(const float* __restrict__ x, float* __restrict__ out) {
    extern __shared__ unsigned char smem[];
    const u32 sbase = smem_u32(smem);
    const int b  = blockIdx.y;
    const int w0 = blockIdx.x * W_TILE;
    const int t  = threadIdx.x;
    const int wid = t >> 5, lane = t & 31;

    float* xs   = (float*)(smem + OFF_XS);
    float* invs = (float*)(smem + OFF_INV);

    // ---- Prologue: stage raw x tile (f32) + inv tile + ALL B channels ----
    const float* xb = x + (size_t)b * CC * LL;
    for (int idx = t; idx < CC * XS_STRIDE; idx += NT) {
        int c = idx / XS_STRIDE, j = idx - c * XS_STRIDE;
        int gw = w0 + j;
        xs[idx] = (gw < LL) ? xb[(size_t)c * LL + gw] : 0.0f;
    }
    for (int idx = t; idx < CC * W_TILE; idx += NT) {
        int c = idx >> 8, j = idx & (W_TILE - 1);
        int gw = w0 + j;
        invs[idx] = (gw < WW) ? g_invn[((size_t)b * CC + c) * WW + gw] : 0.0f;
    }
    {
        const uint4* src = (const uint4*)g_shb;
        uint4* dst = (uint4*)(smem + OFF_B);
        #pragma unroll
        for (int i = 0; i < (CC * 8192 / 16) / NT; ++i)
            dst[t + i * NT] = src[t + i * NT];
    }
    __syncthreads();

    // ---- Build fp16 parity copies for ALL channels (once) ----
    // word layout: [c*2+p][w]; copy_p word w = (x[2w+p], x[2w+p+1]) of channel c.
    for (int idx = t; idx < 16 * 2 * 176; idx += NT) {
        int w = idx % 176;
        int r = idx / 176;            // c*2+p
        int p = r & 1, c = r >> 1;
        int e = 2 * w + p;
        __half2 h2 = __floats2half2_rn(xs[c * XS_STRIDE + e], xs[c * XS_STRIDE + e + 1]);
        *(u32*)(smem + OFF_XHL + r * PLEN_B + w * 4) = *(u32*)&h2;
    }
    __syncthreads();

    // ---- Fragment addressing ----
    const int g  = lane >> 2, q = lane & 3;
    const int e0 = (wid & 7) * 32 + g + 2 * q;
    const int pA = g & 1;
    const int rx    = lane & 7;
    const int bn8   = (lane >> 4) & 1;
    const int bhalf = (lane >> 3) & 1;
    const int pbase = (wid >> 3) * 2;       // k-half ntile-pair base

    float acc[32];                          // [m(2)][nt(4)][4]
    #pragma unroll
    for (int i = 0; i < 32; ++i) acc[i] = 0.0f;

    for (int c = 0; c < CC; ++c) {
        const u32 Bb = sbase + OFF_B + (u32)c * 8192;

        // A: 11 t-loads (covers both m-tiles x 4 k-steps via Hankel collapse:
        // a1==a2, a3(j)==a0(j+1)).
        u32 th[11];
        {
            u32 aH = sbase + OFF_XHL + (u32)(c * 2 + pA) * PLEN_B + (u32)(e0 - pA) * 2;
            #pragma unroll
            for (int i = 0; i < 11; ++i) th[i] = lds32(aH + 16 * i);
        }

        float dot[32];
        #pragma unroll
        for (int i = 0; i < 32; ++i) dot[i] = 0.0f;

        #pragma unroll
        for (int j = 0; j < 4; ++j) {
            u32 bch = (u32)(((2 * j + bhalf) ^ rx) * 16);
            #pragma unroll
            for (int p = 0; p < 2; ++p) {
                u32 boff = (u32)(((pbase + p) * 16 + bn8 * 8 + rx) * 128) + bch;
                u32 b0, b1, b2, b3;
                ldsm4(b0, b1, b2, b3, Bb + boff);
                float* d00 = dot + (0 * 4 + 2 * p) * 4;
                float* d01 = dot + (0 * 4 + 2 * p + 1) * 4;
                float* d10 = dot + (1 * 4 + 2 * p) * 4;
                float* d11 = dot + (1 * 4 + 2 * p + 1) * 4;
                mma_f16(d00, th[2*j], th[2*j+1], th[2*j+1], th[2*j+2], b0, b1);
                mma_f16(d01, th[2*j], th[2*j+1], th[2*j+1], th[2*j+2], b2, b3);
                mma_f16(d10, th[2*j+2], th[2*j+3], th[2*j+3], th[2*j+4], b0, b1);
                mma_f16(d11, th[2*j+2], th[2*j+3], th[2*j+3], th[2*j+4], b2, b3);
            }
        }

        // Fold: acc += inv[c, row] * dot (rows g, g+8, g+16, g+24 of tile)
        {
            const float* ivp = invs + c * W_TILE + (wid & 7) * 32;
            float iv0 = ivp[g], iv1 = ivp[g + 8], iv2 = ivp[g + 16], iv3 = ivp[g + 24];
            #pragma unroll
            for (int nt = 0; nt < 4; ++nt) {
                acc[nt * 4 + 0]      = fmaf(iv0, dot[nt * 4 + 0],      acc[nt * 4 + 0]);
                acc[nt * 4 + 1]      = fmaf(iv0, dot[nt * 4 + 1],      acc[nt * 4 + 1]);
                acc[nt * 4 + 2]      = fmaf(iv1, dot[nt * 4 + 2],      acc[nt * 4 + 2]);
                acc[nt * 4 + 3]      = fmaf(iv1, dot[nt * 4 + 3],      acc[nt * 4 + 3]);
                acc[16 + nt * 4 + 0] = fmaf(iv2, dot[16 + nt * 4 + 0], acc[16 + nt * 4 + 0]);
                acc[16 + nt * 4 + 1] = fmaf(iv2, dot[16 + nt * 4 + 1], acc[16 + nt * 4 + 1]);
                acc[16 + nt * 4 + 2] = fmaf(iv3, dot[16 + nt * 4 + 2], acc[16 + nt * 4 + 2]);
                acc[16 + nt * 4 + 3] = fmaf(iv3, dot[16 + nt * 4 + 3], acc[16 + nt * 4 + 3]);
            }
        }
    }

    // ---- epilogue: max over w per k ----
    float cm[8];
    #pragma unroll
    for (int nt = 0; nt < 4; ++nt) {
        cm[2 * nt] = fmaxf(fmaxf(acc[nt * 4 + 0], acc[nt * 4 + 2]),
                           fmaxf(acc[16 + nt * 4 + 0], acc[16 + nt * 4 + 2]));
        cm[2 * nt + 1] = fmaxf(fmaxf(acc[nt * 4 + 1], acc[nt * 4 + 3]),
                               fmaxf(acc[16 + nt * 4 + 1], acc[16 + nt * 4 + 3]));
    }
    #pragma unroll
    for (int m = 4; m < 32; m <<= 1) {
        #pragma unroll
        for (int i = 0; i < 8; ++i)
            cm[i] = fmaxf(cm[i], __shfl_xor_sync(0xffffffffu, cm[i], m));
    }
    __syncthreads();                        // all B/A smem reads done
    float* red = (float*)(smem + OFF_XHL);  // [16 warps][64 cols]
    if (lane < 4) {
        int kb = (wid >> 3) * 32;
        #pragma unroll
        for (int nt = 0; nt < 4; ++nt) {
            red[wid * 64 + kb + nt * 8 + lane * 2 + 0] = cm[2 * nt];
            red[wid * 64 + kb + nt * 8 + lane * 2 + 1] = cm[2 * nt + 1];
        }
    }
    __syncthreads();
    if (t < KK) {
        int g0 = (t >> 5) * 8;              // warps holding this k-half
        float m = 0.0f;                     // relu floor
        #pragma unroll
        for (int i = 0; i < 8; ++i) m = fmaxf(m, red[(g0 + i) * 64 + t]);
        m *= (1.0f / (float)CC);
        // m >= 0: float bits monotone, int atomicMax exact (out zero-initialized).
        atomicMax((int*)&out[b * KK + t], __float_as_int(m));
    }
}

// ---------------------------------------------------------------------------
// Launch
// ---------------------------------------------------------------------------
extern "C" void kernel_launch(void* const* d_in, const int* in_sizes, int n_in,
                              void* d_out, int out_size) {
    const float* x  = (const float*)d_in[0];   // (32,16,4096) f32
    const float* sh = (const float*)d_in[1];   // (16,64,64)  f32
    float* out = (float*)d_out;                // (32,1,64)   f32

    cudaFuncSetAttribute(max_cossim_kernel,
                         cudaFuncAttributeMaxDynamicSharedMemorySize, SMEM_BYTES);

    norm_shapelets_kernel<<<CC * KK, 32>>>(sh, out);
    win_invnorm_kernel<<<BB * CC, 256>>>(x);

    dim3 grid((WW + W_TILE - 1) / W_TILE, BB);   // (16, 32)
    max_cossim_kernel<<<grid, NT, SMEM_BYTES>>>(x, out);
}

// round 14
// speedup vs baseline: 2.7176x; 1.1971x over previous
#include <cuda_runtime.h>
#include <cuda_fp16.h>
#include <math.h>

// Problem constants
#define BB 32
#define CC 16
#define LL 4096
#define SS 64
#define KK 64
#define WW 4033            // LL - SS + 1

#define W_TILE 128
#define NT 256             // 8 warps: wid&3 -> m32 tile, wid>>2 -> k-half (n32)
#define XS_STRIDE 200      // f32 staging elems per c (need 192)
#define PLEN_B 400         // bytes per parity copy (addressing stride; 96 words built)
#define PWORDS 96          // words built per copy (A reads word index <= 94)

// ---------------- dynamic smem layout (bytes) ----------------
#define OFF_XHL 0                              // [c][p] fp16 parity copies: 16*2*400 = 12800
#define OFF_B   12800                          // 2 x 8192 = 16384 (double-buffered)
#define OFF_INV 29184                          // CC*W_TILE floats = 8192
#define OFF_XS  37376                          // CC*XS_STRIDE f32 = 12800
#define SMEM_BYTES 50176

typedef unsigned int u32;

// Global scratch
__device__ __align__(16) unsigned char g_shb[CC * 8192];  // per-c swizzled fp16 B image

// ---------------- helpers ----------------
__device__ __forceinline__ u32 smem_u32(const void* p) {
    u32 a;
    asm("{ .reg .u64 t; cvta.to.shared.u64 t, %1; cvt.u32.u64 %0, t; }" : "=r"(a) : "l"(p));
    return a;
}
__device__ __forceinline__ u32 swz128(u32 off) { return off ^ ((off >> 3) & 0x70); }

__device__ __forceinline__ void ldsm4(u32& r0, u32& r1, u32& r2, u32& r3, u32 addr) {
    asm volatile("ldmatrix.sync.aligned.m8n8.x4.shared.b16 {%0,%1,%2,%3}, [%4];"
                 : "=r"(r0), "=r"(r1), "=r"(r2), "=r"(r3) : "r"(addr));
}
__device__ __forceinline__ u32 lds32(u32 addr) {
    u32 v;
    asm volatile("ld.shared.b32 %0, [%1];" : "=r"(v) : "r"(addr));
    return v;
}
__device__ __forceinline__ void mma_f16(float* d, u32 a0, u32 a1, u32 a2, u32 a3,
                                        u32 b0, u32 b1) {
    asm volatile(
        "mma.sync.aligned.m16n8k16.row.col.f32.f16.f16.f32 "
        "{%0,%1,%2,%3}, {%4,%5,%6,%7}, {%8,%9}, {%0,%1,%2,%3};"
        : "+f"(d[0]), "+f"(d[1]), "+f"(d[2]), "+f"(d[3])
        : "r"(a0), "r"(a1), "r"(a2), "r"(a3), "r"(b0), "r"(b1));
}

// ---------------------------------------------------------------------------
// Prep: normalize shapelets, fp16, write swizzled B image per c.
// Blocks 0..63 additionally zero the 2048-float output.
// ---------------------------------------------------------------------------
__global__ void norm_shapelets_kernel(const float* __restrict__ sh,
                                      float* __restrict__ out) {
    int row  = blockIdx.x;          // c*KK + k
    int c    = row / KK;
    int k    = row - c * KK;
    int lane = threadIdx.x;
    if (row < 64) out[row * 32 + lane] = 0.0f;   // zero out (64*32 = 2048)
    const float* p = sh + (size_t)row * SS;
    float v0 = p[lane];
    float v1 = p[lane + 32];
    float ss = v0 * v0 + v1 * v1;
    #pragma unroll
    for (int o = 16; o > 0; o >>= 1) ss += __shfl_xor_sync(0xffffffffu, ss, o);
    float inv = 1.0f / fmaxf(sqrtf(ss), 1e-8f);

    unsigned char* img = g_shb + c * 8192;
    #pragma unroll
    for (int h = 0; h < 2; ++h) {
        int s = lane + 32 * h;
        float vn = (h ? v1 : v0) * inv;
        __half hv = __float2half_rn(vn);
        u32 sw = swz128((u32)(k * 128 + s * 2));
        *(unsigned short*)(img + sw) = *(unsigned short*)&hv;
    }
}

__device__ __forceinline__ float inv_norm(float ss) {
    return (ss > 1e-16f) ? rsqrtf(ss) : 1e8f;
}

// ---------------------------------------------------------------------------
// Main: per (b, 128-w tile). Single-term fp16 MMA; Hankel A = 11 broadcast
// LDS.32 per warp per c from prologue-built parity copies. B double-buffered
// 8KB/c from L2-resident image. Window inv-norms computed inline in the
// prologue (sliding sum-of-squares) and folded per-c in fp32.
// ---------------------------------------------------------------------------
__global__ void __launch_bounds__(NT, 2)
max_cossim_kernel(const float* __restrict__ x, float* __restrict__ out) {
    extern __shared__ unsigned char smem[];
    const u32 sbase = smem_u32(smem);
    const int b  = blockIdx.y;
    const int w0 = blockIdx.x * W_TILE;
    const int t  = threadIdx.x;
    const int wid = t >> 5, lane = t & 31;

    float* xs   = (float*)(smem + OFF_XS);
    float* invs = (float*)(smem + OFF_INV);

    // ---- Prologue 1: stage raw x tile (f32, zero-padded) ----
    const float* xb = x + (size_t)b * CC * LL;
    for (int idx = t; idx < CC * XS_STRIDE; idx += NT) {
        int c = idx / XS_STRIDE, j = idx - c * XS_STRIDE;
        int gw = w0 + j;
        xs[idx] = (gw < LL && j < 192) ? xb[(size_t)c * LL + gw] : 0.0f;
    }
    __syncthreads();

    // ---- Prologue 2a: inline window inv-norms (8 windows per thread) ----
    {
        int c  = t >> 4;
        int wb = (t & 15) * 8;
        const float* xr = xs + c * XS_STRIDE + wb;
        float* dst = invs + c * W_TILE + wb;
        float ss = 0.0f;
        #pragma unroll
        for (int s = 0; s < SS; ++s) { float v = xr[s]; ss = fmaf(v, v, ss); }
        dst[0] = (w0 + wb < WW) ? inv_norm(ss) : 0.0f;
        #pragma unroll
        for (int j = 1; j < 8; ++j) {
            float a = xr[j + SS - 1], s0 = xr[j - 1];
            ss = fmaf(a, a, ss);
            ss = fmaf(-s0, s0, ss);
            dst[j] = (w0 + wb + j < WW) ? inv_norm(ss) : 0.0f;
        }
    }
    // ---- Prologue 2b: fp16 parity copies for all channels ----
    // word layout: [c*2+p][w], w < PWORDS=96 (A reads word index <= 94).
    // copy_p word w = (x[2w+p], x[2w+p+1]); max element read = 2*95+1+1 = 192 < 200.
    for (int idx = t; idx < 16 * 2 * PWORDS; idx += NT) {
        int w = idx % PWORDS;
        int r = idx / PWORDS;         // c*2+p
        int p = r & 1, c = r >> 1;
        int e = 2 * w + p;
        __half2 h2 = __floats2half2_rn(xs[c * XS_STRIDE + e], xs[c * XS_STRIDE + e + 1]);
        *(u32*)(smem + OFF_XHL + r * PLEN_B + w * 4) = *(u32*)&h2;
    }
    // ---- Prologue 2c: stage B for c=0 into buf 0 ----
    {
        const uint4* src = (const uint4*)g_shb;
        uint4* dst = (uint4*)(smem + OFF_B);
        dst[t] = src[t]; dst[t + 256] = src[t + 256];
    }
    __syncthreads();

    // ---- Fragment addressing ----
    const int g  = lane >> 2, q = lane & 3;
    const int e0 = (wid & 3) * 32 + g + 2 * q;
    const int pA = g & 1;
    const int rx    = lane & 7;
    const int bn8   = (lane >> 4) & 1;
    const int bhalf = (lane >> 3) & 1;
    const int pbase = (wid >> 2) * 2;       // k-half ntile-pair base

    float acc[32];                          // [m(2)][nt(4)][4]
    #pragma unroll
    for (int i = 0; i < 32; ++i) acc[i] = 0.0f;

    int buf = 0;
    for (int c = 0; c < CC; ++c) {
        // Prefetch B for c+1 into the other buffer (overlaps compute).
        if (c + 1 < CC) {
            const uint4* src = (const uint4*)(g_shb + (size_t)(c + 1) * 8192);
            uint4* dst = (uint4*)(smem + OFF_B + (buf ^ 1) * 8192);
            dst[t] = src[t]; dst[t + 256] = src[t + 256];
        }

        const u32 Bb = sbase + OFF_B + (u32)buf * 8192;

        // A: 11 t-loads (both m16-subtiles x 4 k-steps via Hankel collapse:
        // a1==a2, a3(j)==a0(j+1)).
        u32 th[11];
        {
            u32 aH = sbase + OFF_XHL + (u32)(c * 2 + pA) * PLEN_B + (u32)(e0 - pA) * 2;
            #pragma unroll
            for (int i = 0; i < 11; ++i) th[i] = lds32(aH + 16 * i);
        }

        float dot[32];
        #pragma unroll
        for (int i = 0; i < 32; ++i) dot[i] = 0.0f;

        #pragma unroll
        for (int j = 0; j < 4; ++j) {
            u32 bch = (u32)(((2 * j + bhalf) ^ rx) * 16);
            #pragma unroll
            for (int p = 0; p < 2; ++p) {
                u32 boff = (u32)(((pbase + p) * 16 + bn8 * 8 + rx) * 128) + bch;
                u32 b0, b1, b2, b3;
                ldsm4(b0, b1, b2, b3, Bb + boff);
                float* d00 = dot + (0 * 4 + 2 * p) * 4;
                float* d01 = dot + (0 * 4 + 2 * p + 1) * 4;
                float* d10 = dot + (1 * 4 + 2 * p) * 4;
                float* d11 = dot + (1 * 4 + 2 * p + 1) * 4;
                mma_f16(d00, th[2*j], th[2*j+1], th[2*j+1], th[2*j+2], b0, b1);
                mma_f16(d01, th[2*j], th[2*j+1], th[2*j+1], th[2*j+2], b2, b3);
                mma_f16(d10, th[2*j+2], th[2*j+3], th[2*j+3], th[2*j+4], b0, b1);
                mma_f16(d11, th[2*j+2], th[2*j+3], th[2*j+3], th[2*j+4], b2, b3);
            }
        }

        // Fold: acc += inv[c, row] * dot (rows g, g+8, g+16, g+24 of m-tile)
        {
            const float* ivp = invs + c * W_TILE + (wid & 3) * 32;
            float iv0 = ivp[g], iv1 = ivp[g + 8], iv2 = ivp[g + 16], iv3 = ivp[g + 24];
            #pragma unroll
            for (int nt = 0; nt < 4; ++nt) {
                acc[nt * 4 + 0]      = fmaf(iv0, dot[nt * 4 + 0],      acc[nt * 4 + 0]);
                acc[nt * 4 + 1]      = fmaf(iv0, dot[nt * 4 + 1],      acc[nt * 4 + 1]);
                acc[nt * 4 + 2]      = fmaf(iv1, dot[nt * 4 + 2],      acc[nt * 4 + 2]);
                acc[nt * 4 + 3]      = fmaf(iv1, dot[nt * 4 + 3],      acc[nt * 4 + 3]);
                acc[16 + nt * 4 + 0] = fmaf(iv2, dot[16 + nt * 4 + 0], acc[16 + nt * 4 + 0]);
                acc[16 + nt * 4 + 1] = fmaf(iv2, dot[16 + nt * 4 + 1], acc[16 + nt * 4 + 1]);
                acc[16 + nt * 4 + 2] = fmaf(iv3, dot[16 + nt * 4 + 2], acc[16 + nt * 4 + 2]);
                acc[16 + nt * 4 + 3] = fmaf(iv3, dot[16 + nt * 4 + 3], acc[16 + nt * 4 + 3]);
            }
        }
        __syncthreads();   // B(c+1) staged; B(c) reads done
        buf ^= 1;
    }

    // ---- epilogue: max over w per k ----
    float cm[8];
    #pragma unroll
    for (int nt = 0; nt < 4; ++nt) {
        cm[2 * nt] = fmaxf(fmaxf(acc[nt * 4 + 0], acc[nt * 4 + 2]),
                           fmaxf(acc[16 + nt * 4 + 0], acc[16 + nt * 4 + 2]));
        cm[2 * nt + 1] = fmaxf(fmaxf(acc[nt * 4 + 1], acc[nt * 4 + 3]),
                               fmaxf(acc[16 + nt * 4 + 1], acc[16 + nt * 4 + 3]));
    }
    #pragma unroll
    for (int m = 4; m < 32; m <<= 1) {
        #pragma unroll
        for (int i = 0; i < 8; ++i)
            cm[i] = fmaxf(cm[i], __shfl_xor_sync(0xffffffffu, cm[i], m));
    }
    float* red = (float*)(smem + OFF_XHL);  // [8 warps][64 cols]
    if (lane < 4) {
        int kb = (wid >> 2) * 32;
        #pragma unroll
        for (int nt = 0; nt < 4; ++nt) {
            red[wid * 64 + kb + nt * 8 + lane * 2 + 0] = cm[2 * nt];
            red[wid * 64 + kb + nt * 8 + lane * 2 + 1] = cm[2 * nt + 1];
        }
    }
    __syncthreads();
    if (t < KK) {
        int g0 = (t >> 5) * 4;              // warps holding this k-half
        float m = 0.0f;                     // relu floor
        #pragma unroll
        for (int i = 0; i < 4; ++i) m = fmaxf(m, red[(g0 + i) * 64 + t]);
        m *= (1.0f / (float)CC);
        // m >= 0: float bits monotone, int atomicMax exact (out zero-initialized).
        atomicMax((int*)&out[b * KK + t], __float_as_int(m));
    }
}

// ---------------------------------------------------------------------------
// Launch
// ---------------------------------------------------------------------------
extern "C" void kernel_launch(void* const* d_in, const int* in_sizes, int n_in,
                              void* d_out, int out_size) {
    const float* x  = (const float*)d_in[0];   // (32,16,4096) f32
    const float* sh = (const float*)d_in[1];   // (16,64,64)  f32
    float* out = (float*)d_out;                // (32,1,64)   f32

    cudaFuncSetAttribute(max_cossim_kernel,
                         cudaFuncAttributeMaxDynamicSharedMemorySize, SMEM_BYTES);

    norm_shapelets_kernel<<<CC * KK, 32>>>(sh, out);

    dim3 grid((WW + W_TILE - 1) / W_TILE, BB);   // (32, 32)
    max_cossim_kernel<<<grid, NT, SMEM_BYTES>>>(x, out);
}

// round 15
// speedup vs baseline: 2.8731x; 1.0572x over previous
#include <cuda_runtime.h>
#include <cuda_fp16.h>
#include <math.h>

// Problem constants
#define BB 32
#define CC 16
#define LL 4096
#define SS 64
#define KK 64
#define WW 4033            // LL - SS + 1

#define W_TILE 128
#define NT 256             // 8 warps: wid&3 -> m32 tile, wid>>2 -> k-half (n32)
#define XS_STRIDE 200      // f32 staging elems per c (need 192)
#define PLEN_B 400         // bytes per parity copy (addressing stride; 96 words built)
#define PWORDS 96          // words built per copy (A reads word index <= 94)

// ---------------- dynamic smem layout (bytes) ----------------
#define OFF_XHL 0                              // [c][p] fp16 parity copies: 16*2*400 = 12800
#define OFF_B   12800                          // 2 x 8192 = 16384 (double-buffered)
#define OFF_INV 29184                          // CC*W_TILE floats = 8192
#define OFF_XS  37376                          // CC*XS_STRIDE f32 = 12800
#define SMEM_BYTES 50176

typedef unsigned int u32;

// Global scratch
__device__ __align__(16) unsigned char g_shb[CC * 8192];  // per-c swizzled fp16 B image

// ---------------- helpers ----------------
__device__ __forceinline__ u32 smem_u32(const void* p) {
    u32 a;
    asm("{ .reg .u64 t; cvta.to.shared.u64 t, %1; cvt.u32.u64 %0, t; }" : "=r"(a) : "l"(p));
    return a;
}
__device__ __forceinline__ u32 swz128(u32 off) { return off ^ ((off >> 3) & 0x70); }

__device__ __forceinline__ void ldsm4(u32& r0, u32& r1, u32& r2, u32& r3, u32 addr) {
    asm volatile("ldmatrix.sync.aligned.m8n8.x4.shared.b16 {%0,%1,%2,%3}, [%4];"
                 : "=r"(r0), "=r"(r1), "=r"(r2), "=r"(r3) : "r"(addr));
}
__device__ __forceinline__ u32 lds32(u32 addr) {
    u32 v;
    asm volatile("ld.shared.b32 %0, [%1];" : "=r"(v) : "r"(addr));
    return v;
}
__device__ __forceinline__ void mma_f16(float* d, u32 a0, u32 a1, u32 a2, u32 a3,
                                        u32 b0, u32 b1) {
    asm volatile(
        "mma.sync.aligned.m16n8k16.row.col.f32.f16.f16.f32 "
        "{%0,%1,%2,%3}, {%4,%5,%6,%7}, {%8,%9}, {%0,%1,%2,%3};"
        : "+f"(d[0]), "+f"(d[1]), "+f"(d[2]), "+f"(d[3])
        : "r"(a0), "r"(a1), "r"(a2), "r"(a3), "r"(b0), "r"(b1));
}

// ---------------------------------------------------------------------------
// Prep: normalize shapelets, fp16, write swizzled B image per c.
// Blocks 0..63 additionally zero the 2048-float output.
// ---------------------------------------------------------------------------
__global__ void norm_shapelets_kernel(const float* __restrict__ sh,
                                      float* __restrict__ out) {
    int row  = blockIdx.x;          // c*KK + k
    int c    = row / KK;
    int k    = row - c * KK;
    int lane = threadIdx.x;
    if (row < 64) out[row * 32 + lane] = 0.0f;   // zero out (64*32 = 2048)
    const float* p = sh + (size_t)row * SS;
    float v0 = p[lane];
    float v1 = p[lane + 32];
    float ss = v0 * v0 + v1 * v1;
    #pragma unroll
    for (int o = 16; o > 0; o >>= 1) ss += __shfl_xor_sync(0xffffffffu, ss, o);
    float inv = 1.0f / fmaxf(sqrtf(ss), 1e-8f);

    unsigned char* img = g_shb + c * 8192;
    #pragma unroll
    for (int h = 0; h < 2; ++h) {
        int s = lane + 32 * h;
        float vn = (h ? v1 : v0) * inv;
        __half hv = __float2half_rn(vn);
        u32 sw = swz128((u32)(k * 128 + s * 2));
        *(unsigned short*)(img + sw) = *(unsigned short*)&hv;
    }
}

__device__ __forceinline__ float inv_norm(float ss) {
    return (ss > 1e-16f) ? rsqrtf(ss) : 1e8f;
}

// ---------------------------------------------------------------------------
// Main: per (b, 128-w tile). Single-term fp16 MMA; Hankel A = 11 broadcast
// LDS.32 per warp per c. B(c+1) LDG'd into REGISTERS at iteration top and
// STS'd just before the barrier -> LDG latency hidden under the MMA block.
// Window inv-norms computed inline in the prologue; inv folded per-c in fp32.
// ---------------------------------------------------------------------------
__global__ void __launch_bounds__(NT, 2)
max_cossim_kernel(const float* __restrict__ x, float* __restrict__ out) {
    extern __shared__ unsigned char smem[];
    const u32 sbase = smem_u32(smem);
    const int b  = blockIdx.y;
    const int w0 = blockIdx.x * W_TILE;
    const int t  = threadIdx.x;
    const int wid = t >> 5, lane = t & 31;

    float* xs   = (float*)(smem + OFF_XS);
    float* invs = (float*)(smem + OFF_INV);

    // ---- Prologue 1: stage raw x tile (f32, zero-padded) ----
    const float* xb = x + (size_t)b * CC * LL;
    for (int idx = t; idx < CC * XS_STRIDE; idx += NT) {
        int c = idx / XS_STRIDE, j = idx - c * XS_STRIDE;
        int gw = w0 + j;
        xs[idx] = (gw < LL && j < 192) ? xb[(size_t)c * LL + gw] : 0.0f;
    }
    __syncthreads();

    // ---- Prologue 2a: inline window inv-norms (8 windows per thread) ----
    {
        int c  = t >> 4;
        int wb = (t & 15) * 8;
        const float* xr = xs + c * XS_STRIDE + wb;
        float* dst = invs + c * W_TILE + wb;
        float ss = 0.0f;
        #pragma unroll
        for (int s = 0; s < SS; ++s) { float v = xr[s]; ss = fmaf(v, v, ss); }
        dst[0] = (w0 + wb < WW) ? inv_norm(ss) : 0.0f;
        #pragma unroll
        for (int j = 1; j < 8; ++j) {
            float a = xr[j + SS - 1], s0 = xr[j - 1];
            ss = fmaf(a, a, ss);
            ss = fmaf(-s0, s0, ss);
            dst[j] = (w0 + wb + j < WW) ? inv_norm(ss) : 0.0f;
        }
    }
    // ---- Prologue 2b: fp16 parity copies for all channels ----
    // word layout: [c*2+p][w], w < PWORDS=96 (A reads word index <= 94).
    for (int idx = t; idx < 16 * 2 * PWORDS; idx += NT) {
        int w = idx % PWORDS;
        int r = idx / PWORDS;         // c*2+p
        int p = r & 1, c = r >> 1;
        int e = 2 * w + p;
        __half2 h2 = __floats2half2_rn(xs[c * XS_STRIDE + e], xs[c * XS_STRIDE + e + 1]);
        *(u32*)(smem + OFF_XHL + r * PLEN_B + w * 4) = *(u32*)&h2;
    }
    // ---- Prologue 2c: stage B for c=0 into buf 0 ----
    {
        const uint4* src = (const uint4*)g_shb;
        uint4* dst = (uint4*)(smem + OFF_B);
        dst[t] = src[t]; dst[t + 256] = src[t + 256];
    }
    __syncthreads();

    // ---- Fragment addressing ----
    const int g  = lane >> 2, q = lane & 3;
    const int e0 = (wid & 3) * 32 + g + 2 * q;
    const int pA = g & 1;
    const int rx    = lane & 7;
    const int bn8   = (lane >> 4) & 1;
    const int bhalf = (lane >> 3) & 1;
    const int pbase = (wid >> 2) * 2;       // k-half ntile-pair base

    float acc[32];                          // [m(2)][nt(4)][4]
    #pragma unroll
    for (int i = 0; i < 32; ++i) acc[i] = 0.0f;

    int buf = 0;
    for (int c = 0; c < CC; ++c) {
        // Issue B(c+1) LDGs into registers NOW; consume (STS) after the MMAs.
        uint4 pf0, pf1;
        const bool havepf = (c + 1 < CC);
        if (havepf) {
            const uint4* src = (const uint4*)(g_shb + (size_t)(c + 1) * 8192);
            pf0 = src[t];
            pf1 = src[t + 256];
        }

        // Hoist fold coefficients (independent LDS, overlap with MMA chain).
        const float* ivp = invs + c * W_TILE + (wid & 3) * 32;
        const float iv0 = ivp[g], iv1 = ivp[g + 8], iv2 = ivp[g + 16], iv3 = ivp[g + 24];

        const u32 Bb = sbase + OFF_B + (u32)buf * 8192;

        // A: 11 t-loads (both m16-subtiles x 4 k-steps via Hankel collapse:
        // a1==a2, a3(j)==a0(j+1)).
        u32 th[11];
        {
            u32 aH = sbase + OFF_XHL + (u32)(c * 2 + pA) * PLEN_B + (u32)(e0 - pA) * 2;
            #pragma unroll
            for (int i = 0; i < 11; ++i) th[i] = lds32(aH + 16 * i);
        }

        float dot[32];
        #pragma unroll
        for (int i = 0; i < 32; ++i) dot[i] = 0.0f;

        #pragma unroll
        for (int j = 0; j < 4; ++j) {
            u32 bch = (u32)(((2 * j + bhalf) ^ rx) * 16);
            #pragma unroll
            for (int p = 0; p < 2; ++p) {
                u32 boff = (u32)(((pbase + p) * 16 + bn8 * 8 + rx) * 128) + bch;
                u32 b0, b1, b2, b3;
                ldsm4(b0, b1, b2, b3, Bb + boff);
                float* d00 = dot + (0 * 4 + 2 * p) * 4;
                float* d01 = dot + (0 * 4 + 2 * p + 1) * 4;
                float* d10 = dot + (1 * 4 + 2 * p) * 4;
                float* d11 = dot + (1 * 4 + 2 * p + 1) * 4;
                mma_f16(d00, th[2*j], th[2*j+1], th[2*j+1], th[2*j+2], b0, b1);
                mma_f16(d01, th[2*j], th[2*j+1], th[2*j+1], th[2*j+2], b2, b3);
                mma_f16(d10, th[2*j+2], th[2*j+3], th[2*j+3], th[2*j+4], b0, b1);
                mma_f16(d11, th[2*j+2], th[2*j+3], th[2*j+3], th[2*j+4], b2, b3);
            }
        }

        // Fold: acc += inv[c, row] * dot (rows g, g+8, g+16, g+24 of m-tile)
        #pragma unroll
        for (int nt = 0; nt < 4; ++nt) {
            acc[nt * 4 + 0]      = fmaf(iv0, dot[nt * 4 + 0],      acc[nt * 4 + 0]);
            acc[nt * 4 + 1]      = fmaf(iv0, dot[nt * 4 + 1],      acc[nt * 4 + 1]);
            acc[nt * 4 + 2]      = fmaf(iv1, dot[nt * 4 + 2],      acc[nt * 4 + 2]);
            acc[nt * 4 + 3]      = fmaf(iv1, dot[nt * 4 + 3],      acc[nt * 4 + 3]);
            acc[16 + nt * 4 + 0] = fmaf(iv2, dot[16 + nt * 4 + 0], acc[16 + nt * 4 + 0]);
            acc[16 + nt * 4 + 1] = fmaf(iv2, dot[16 + nt * 4 + 1], acc[16 + nt * 4 + 1]);
            acc[16 + nt * 4 + 2] = fmaf(iv3, dot[16 + nt * 4 + 2], acc[16 + nt * 4 + 2]);
            acc[16 + nt * 4 + 3] = fmaf(iv3, dot[16 + nt * 4 + 3], acc[16 + nt * 4 + 3]);
        }

        // Write prefetched B(c+1) to the other buffer, then sync.
        if (havepf) {
            uint4* dst = (uint4*)(smem + OFF_B + (buf ^ 1) * 8192);
            dst[t] = pf0;
            dst[t + 256] = pf1;
        }
        __syncthreads();   // B(c+1) staged; B(c) reads done
        buf ^= 1;
    }

    // ---- epilogue: max over w per k ----
    float cm[8];
    #pragma unroll
    for (int nt = 0; nt < 4; ++nt) {
        cm[2 * nt] = fmaxf(fmaxf(acc[nt * 4 + 0], acc[nt * 4 + 2]),
                           fmaxf(acc[16 + nt * 4 + 0], acc[16 + nt * 4 + 2]));
        cm[2 * nt + 1] = fmaxf(fmaxf(acc[nt * 4 + 1], acc[nt * 4 + 3]),
                               fmaxf(acc[16 + nt * 4 + 1], acc[16 + nt * 4 + 3]));
    }
    #pragma unroll
    for (int m = 4; m < 32; m <<= 1) {
        #pragma unroll
        for (int i = 0; i < 8; ++i)
            cm[i] = fmaxf(cm[i], __shfl_xor_sync(0xffffffffu, cm[i], m));
    }
    float* red = (float*)(smem + OFF_XHL);  // [8 warps][64 cols]
    if (lane < 4) {
        int kb = (wid >> 2) * 32;
        #pragma unroll
        for (int nt = 0; nt < 4; ++nt) {
            red[wid * 64 + kb + nt * 8 + lane * 2 + 0] = cm[2 * nt];
            red[wid * 64 + kb + nt * 8 + lane * 2 + 1] = cm[2 * nt + 1];
        }
    }
    __syncthreads();
    if (t < KK) {
        int g0 = (t >> 5) * 4;              // warps holding this k-half
        float m = 0.0f;                     // relu floor
        #pragma unroll
        for (int i = 0; i < 4; ++i) m = fmaxf(m, red[(g0 + i) * 64 + t]);
        m *= (1.0f / (float)CC);
        // m >= 0: float bits monotone, int atomicMax exact (out zero-initialized).
        atomicMax((int*)&out[b * KK + t], __float_as_int(m));
    }
}

// ---------------------------------------------------------------------------
// Launch
// ---------------------------------------------------------------------------
extern "C" void kernel_launch(void* const* d_in, const int* in_sizes, int n_in,
                              void* d_out, int out_size) {
    const float* x  = (const float*)d_in[0];   // (32,16,4096) f32
    const float* sh = (const float*)d_in[1];   // (16,64,64)  f32
    float* out = (float*)d_out;                // (32,1,64)   f32

    cudaFuncSetAttribute(max_cossim_kernel,
                         cudaFuncAttributeMaxDynamicSharedMemorySize, SMEM_BYTES);

    norm_shapelets_kernel<<<CC * KK, 32>>>(sh, out);

    dim3 grid((WW + W_TILE - 1) / W_TILE, BB);   // (32, 32)
    max_cossim_kernel<<<grid, NT, SMEM_BYTES>>>(x, out);
}

// round 16
// speedup vs baseline: 3.1018x; 1.0796x over previous
#include <cuda_runtime.h>
#include <cuda_fp16.h>
#include <math.h>

// Problem constants
#define BB 32
#define CC 16
#define LL 4096
#define SS 64
#define KK 64
#define WW 4033            // LL - SS + 1

#define W_TILE 128
#define NT 256             // 8 warps: wid&3 -> m32 tile, wid>>2 -> k-half (n32)
#define XS_STRIDE 200      // f32 staging elems per c (need 192)
#define PLEN_B 400         // bytes per parity copy (addressing stride; 96 words built)
#define PWORDS 96          // words built per copy (A reads word index <= 94)

// ---------------- dynamic smem layout (bytes) ----------------
#define OFF_XHL 0                              // [c][p] fp16 parity copies: 16*2*400 = 12800
#define OFF_B   12800                          // 4 x 8192 = 32768 (two 2-buffer sets)
#define OFF_INV 45568                          // CC*W_TILE floats = 8192
#define OFF_XS  53760                          // CC*XS_STRIDE f32 = 12800
#define SMEM_BYTES 66560

typedef unsigned int u32;

// Global scratch
__device__ __align__(16) unsigned char g_shb[CC * 8192];  // per-c swizzled fp16 B image

// ---------------- helpers ----------------
__device__ __forceinline__ u32 smem_u32(const void* p) {
    u32 a;
    asm("{ .reg .u64 t; cvta.to.shared.u64 t, %1; cvt.u32.u64 %0, t; }" : "=r"(a) : "l"(p));
    return a;
}
__device__ __forceinline__ u32 swz128(u32 off) { return off ^ ((off >> 3) & 0x70); }

__device__ __forceinline__ void cp16(u32 dst, const void* src) {
    asm volatile("cp.async.cg.shared.global [%0], [%1], 16;"
                 :: "r"(dst), "l"(src) : "memory");
}
#define CP_COMMIT() asm volatile("cp.async.commit_group;" ::: "memory")
#define CP_WAIT0()  asm volatile("cp.async.wait_group 0;" ::: "memory")

__device__ __forceinline__ void ldsm4(u32& r0, u32& r1, u32& r2, u32& r3, u32 addr) {
    asm volatile("ldmatrix.sync.aligned.m8n8.x4.shared.b16 {%0,%1,%2,%3}, [%4];"
                 : "=r"(r0), "=r"(r1), "=r"(r2), "=r"(r3) : "r"(addr));
}
__device__ __forceinline__ u32 lds32(u32 addr) {
    u32 v;
    asm volatile("ld.shared.b32 %0, [%1];" : "=r"(v) : "r"(addr));
    return v;
}
__device__ __forceinline__ void mma_f16(float* d, u32 a0, u32 a1, u32 a2, u32 a3,
                                        u32 b0, u32 b1) {
    asm volatile(
        "mma.sync.aligned.m16n8k16.row.col.f32.f16.f16.f32 "
        "{%0,%1,%2,%3}, {%4,%5,%6,%7}, {%8,%9}, {%0,%1,%2,%3};"
        : "+f"(d[0]), "+f"(d[1]), "+f"(d[2]), "+f"(d[3])
        : "r"(a0), "r"(a1), "r"(a2), "r"(a3), "r"(b0), "r"(b1));
}

// ---------------------------------------------------------------------------
// Prep: normalize shapelets, fp16, write swizzled B image per c.
// Blocks 0..63 additionally zero the 2048-float output.
// ---------------------------------------------------------------------------
__global__ void norm_shapelets_kernel(const float* __restrict__ sh,
                                      float* __restrict__ out) {
    int row  = blockIdx.x;          // c*KK + k
    int c    = row / KK;
    int k    = row - c * KK;
    int lane = threadIdx.x;
    if (row < 64) out[row * 32 + lane] = 0.0f;   // zero out (64*32 = 2048)
    const float* p = sh + (size_t)row * SS;
    float v0 = p[lane];
    float v1 = p[lane + 32];
    float ss = v0 * v0 + v1 * v1;
    #pragma unroll
    for (int o = 16; o > 0; o >>= 1) ss += __shfl_xor_sync(0xffffffffu, ss, o);
    float inv = 1.0f / fmaxf(sqrtf(ss), 1e-8f);

    unsigned char* img = g_shb + c * 8192;
    #pragma unroll
    for (int h = 0; h < 2; ++h) {
        int s = lane + 32 * h;
        float vn = (h ? v1 : v0) * inv;
        __half hv = __float2half_rn(vn);
        u32 sw = swz128((u32)(k * 128 + s * 2));
        *(unsigned short*)(img + sw) = *(unsigned short*)&hv;
    }
}

__device__ __forceinline__ float inv_norm(float ss) {
    return (ss > 1e-16f) ? rsqrtf(ss) : 1e8f;
}

// ---------------------------------------------------------------------------
// Main: per (b, 128-w tile). Single-term fp16 MMA; Hankel A = 11 broadcast
// LDS.32 per warp per c. Channels processed in PAIRS: cp.async stages the
// next 2-channel B set while the current set computes -> 8 barriers, 64
// independent MMAs per span. inv-norms inline in prologue; fp32 fold per c.
// ---------------------------------------------------------------------------
__global__ void __launch_bounds__(NT, 2)
max_cossim_kernel(const float* __restrict__ x, float* __restrict__ out) {
    extern __shared__ unsigned char smem[];
    const u32 sbase = smem_u32(smem);
    const int b  = blockIdx.y;
    const int w0 = blockIdx.x * W_TILE;
    const int t  = threadIdx.x;
    const int wid = t >> 5, lane = t & 31;

    float* xs   = (float*)(smem + OFF_XS);
    float* invs = (float*)(smem + OFF_INV);

    // B staging: 8192 B per channel, 32 B per thread via 2 cp.async.
    auto stageB = [&](int cc, int bufidx) {
        const unsigned char* src = g_shb + (size_t)cc * 8192;
        u32 dst = sbase + OFF_B + (u32)bufidx * 8192;
        cp16(dst + t * 16,        src + t * 16);
        cp16(dst + t * 16 + 4096, src + t * 16 + 4096);
    };

    // ---- Prologue 1: stage raw x tile (f32, zero-padded) ----
    const float* xb = x + (size_t)b * CC * LL;
    for (int idx = t; idx < CC * XS_STRIDE; idx += NT) {
        int c = idx / XS_STRIDE, j = idx - c * XS_STRIDE;
        int gw = w0 + j;
        xs[idx] = (gw < LL && j < 192) ? xb[(size_t)c * LL + gw] : 0.0f;
    }
    // Kick off B staging for channels 0,1 (overlaps with prologue 2).
    stageB(0, 0);
    stageB(1, 1);
    CP_COMMIT();
    __syncthreads();

    // ---- Prologue 2a: inline window inv-norms (8 windows per thread) ----
    {
        int c  = t >> 4;
        int wb = (t & 15) * 8;
        const float* xr = xs + c * XS_STRIDE + wb;
        float* dst = invs + c * W_TILE + wb;
        float ss = 0.0f;
        #pragma unroll
        for (int s = 0; s < SS; ++s) { float v = xr[s]; ss = fmaf(v, v, ss); }
        dst[0] = (w0 + wb < WW) ? inv_norm(ss) : 0.0f;
        #pragma unroll
        for (int j = 1; j < 8; ++j) {
            float a = xr[j + SS - 1], s0 = xr[j - 1];
            ss = fmaf(a, a, ss);
            ss = fmaf(-s0, s0, ss);
            dst[j] = (w0 + wb + j < WW) ? inv_norm(ss) : 0.0f;
        }
    }
    // ---- Prologue 2b: fp16 parity copies for all channels ----
    // word layout: [c*2+p][w], w < PWORDS=96 (A reads word index <= 94).
    for (int idx = t; idx < 16 * 2 * PWORDS; idx += NT) {
        int w = idx % PWORDS;
        int r = idx / PWORDS;         // c*2+p
        int p = r & 1, c = r >> 1;
        int e = 2 * w + p;
        __half2 h2 = __floats2half2_rn(xs[c * XS_STRIDE + e], xs[c * XS_STRIDE + e + 1]);
        *(u32*)(smem + OFF_XHL + r * PLEN_B + w * 4) = *(u32*)&h2;
    }
    CP_WAIT0();
    __syncthreads();

    // ---- Fragment addressing ----
    const int g  = lane >> 2, q = lane & 3;
    const int e0 = (wid & 3) * 32 + g + 2 * q;
    const int pA = g & 1;
    const int rx    = lane & 7;
    const int bn8   = (lane >> 4) & 1;
    const int bhalf = (lane >> 3) & 1;
    const int pbase = (wid >> 2) * 2;       // k-half ntile-pair base

    float acc[32];                          // [m(2)][nt(4)][4]
    #pragma unroll
    for (int i = 0; i < 32; ++i) acc[i] = 0.0f;

    // Per-channel compute: A t-loads (Hankel collapse: a1==a2, a3(j)==a0(j+1)),
    // 32 MMAs, fp32 fold of inv.
    auto compute_c = [&](int c, u32 Bb) {
        const float* ivp = invs + c * W_TILE + (wid & 3) * 32;
        const float iv0 = ivp[g], iv1 = ivp[g + 8], iv2 = ivp[g + 16], iv3 = ivp[g + 24];

        u32 th[11];
        {
            u32 aH = sbase + OFF_XHL + (u32)(c * 2 + pA) * PLEN_B + (u32)(e0 - pA) * 2;
            #pragma unroll
            for (int i = 0; i < 11; ++i) th[i] = lds32(aH + 16 * i);
        }

        float dot[32];
        #pragma unroll
        for (int i = 0; i < 32; ++i) dot[i] = 0.0f;

        #pragma unroll
        for (int j = 0; j < 4; ++j) {
            u32 bch = (u32)(((2 * j + bhalf) ^ rx) * 16);
            #pragma unroll
            for (int p = 0; p < 2; ++p) {
                u32 boff = (u32)(((pbase + p) * 16 + bn8 * 8 + rx) * 128) + bch;
                u32 b0, b1, b2, b3;
                ldsm4(b0, b1, b2, b3, Bb + boff);
                float* d00 = dot + (0 * 4 + 2 * p) * 4;
                float* d01 = dot + (0 * 4 + 2 * p + 1) * 4;
                float* d10 = dot + (1 * 4 + 2 * p) * 4;
                float* d11 = dot + (1 * 4 + 2 * p + 1) * 4;
                mma_f16(d00, th[2*j], th[2*j+1], th[2*j+1], th[2*j+2], b0, b1);
                mma_f16(d01, th[2*j], th[2*j+1], th[2*j+1], th[2*j+2], b2, b3);
                mma_f16(d10, th[2*j+2], th[2*j+3], th[2*j+3], th[2*j+4], b0, b1);
                mma_f16(d11, th[2*j+2], th[2*j+3], th[2*j+3], th[2*j+4], b2, b3);
            }
        }

        #pragma unroll
        for (int nt = 0; nt < 4; ++nt) {
            acc[nt * 4 + 0]      = fmaf(iv0, dot[nt * 4 + 0],      acc[nt * 4 + 0]);
            acc[nt * 4 + 1]      = fmaf(iv0, dot[nt * 4 + 1],      acc[nt * 4 + 1]);
            acc[nt * 4 + 2]      = fmaf(iv1, dot[nt * 4 + 2],      acc[nt * 4 + 2]);
            acc[nt * 4 + 3]      = fmaf(iv1, dot[nt * 4 + 3],      acc[nt * 4 + 3]);
            acc[16 + nt * 4 + 0] = fmaf(iv2, dot[16 + nt * 4 + 0], acc[16 + nt * 4 + 0]);
            acc[16 + nt * 4 + 1] = fmaf(iv2, dot[16 + nt * 4 + 1], acc[16 + nt * 4 + 1]);
            acc[16 + nt * 4 + 2] = fmaf(iv3, dot[16 + nt * 4 + 2], acc[16 + nt * 4 + 2]);
            acc[16 + nt * 4 + 3] = fmaf(iv3, dot[16 + nt * 4 + 3], acc[16 + nt * 4 + 3]);
        }
    };

    // ---- Mainloop: 2 channels per barrier; cp.async next set meanwhile ----
    #pragma unroll 1
    for (int cs = 0; cs < CC; cs += 2) {
        const int s = (cs >> 1) & 1;                 // current buffer set
        if (cs + 2 < CC) {
            stageB(cs + 2, (s ^ 1) * 2);
            stageB(cs + 3, (s ^ 1) * 2 + 1);
            CP_COMMIT();
        }
        compute_c(cs,     sbase + OFF_B + (u32)(s * 2) * 8192);
        compute_c(cs + 1, sbase + OFF_B + (u32)(s * 2 + 1) * 8192);
        if (cs + 2 < CC) CP_WAIT0();
        __syncthreads();   // next set landed for all warps; current reads done
    }

    // ---- epilogue: max over w per k ----
    float cm[8];
    #pragma unroll
    for (int nt = 0; nt < 4; ++nt) {
        cm[2 * nt] = fmaxf(fmaxf(acc[nt * 4 + 0], acc[nt * 4 + 2]),
                           fmaxf(acc[16 + nt * 4 + 0], acc[16 + nt * 4 + 2]));
        cm[2 * nt + 1] = fmaxf(fmaxf(acc[nt * 4 + 1], acc[nt * 4 + 3]),
                               fmaxf(acc[16 + nt * 4 + 1], acc[16 + nt * 4 + 3]));
    }
    #pragma unroll
    for (int m = 4; m < 32; m <<= 1) {
        #pragma unroll
        for (int i = 0; i < 8; ++i)
            cm[i] = fmaxf(cm[i], __shfl_xor_sync(0xffffffffu, cm[i], m));
    }
    float* red = (float*)(smem + OFF_XHL);  // [8 warps][64 cols]
    if (lane < 4) {
        int kb = (wid >> 2) * 32;
        #pragma unroll
        for (int nt = 0; nt < 4; ++nt) {
            red[wid * 64 + kb + nt * 8 + lane * 2 + 0] = cm[2 * nt];
            red[wid * 64 + kb + nt * 8 + lane * 2 + 1] = cm[2 * nt + 1];
        }
    }
    __syncthreads();
    if (t < KK) {
        int g0 = (t >> 5) * 4;              // warps holding this k-half
        float m = 0.0f;                     // relu floor
        #pragma unroll
        for (int i = 0; i < 4; ++i) m = fmaxf(m, red[(g0 + i) * 64 + t]);
        m *= (1.0f / (float)CC);
        // m >= 0: float bits monotone, int atomicMax exact (out zero-initialized).
        atomicMax((int*)&out[b * KK + t], __float_as_int(m));
    }
}

// ---------------------------------------------------------------------------
// Launch
// ---------------------------------------------------------------------------
extern "C" void kernel_launch(void* const* d_in, const int* in_sizes, int n_in,
                              void* d_out, int out_size) {
    const float* x  = (const float*)d_in[0];   // (32,16,4096) f32
    const float* sh = (const float*)d_in[1];   // (16,64,64)  f32
    float* out = (float*)d_out;                // (32,1,64)   f32

    cudaFuncSetAttribute(max_cossim_kernel,
                         cudaFuncAttributeMaxDynamicSharedMemorySize, SMEM_BYTES);

    norm_shapelets_kernel<<<CC * KK, 32>>>(sh, out);

    dim3 grid((WW + W_TILE - 1) / W_TILE, BB);   // (32, 32)
    max_cossim_kernel<<<grid, NT, SMEM_BYTES>>>(x, out);
}